// round 1
// baseline (speedup 1.0000x reference)
#include <cuda_runtime.h>

// FlowLenia single step. SX=SY=256, C=3, K=15, DD=5, DT=0.2, SIGMA=0.65
// Output: newA (256*256*3) followed by newP (256*256*15), float32.

#define NPIX 65536
static __device__ float2 g_fA[3 * NPIX];    // FFT2(A) per channel, [c][x][y]
static __device__ float2 g_tmp[15 * NPIX];  // per-kernel spectral workspace, [k][x][y]
static __device__ float  g_G[15 * NPIX];    // growth(U)*P, [k][x][y]
static __device__ float4 g_UcAs[NPIX];      // (Uc0,Uc1,Uc2,Asum) per pixel
static __device__ float  g_mu[NPIX * 6];    // mu per pixel: [row_c0..2, col_c0..2]

__device__ __forceinline__ float2 cmulf(float2 a, float2 b) {
    return make_float2(a.x * b.x - a.y * b.y, a.x * b.y + a.y * b.x);
}

// Stockham DIF radix-2, 256-point, NB transforms per 256-thread block.
// TS = shared stride per transform (padding for column kernels).
// Result lands back in bufA in natural order (8 stages, even ping-pong).
template <int NB, int TS, bool INV>
__device__ __forceinline__ void fft256(float2* bufA, float2* bufB) {
    float2* src = bufA;
    float2* dst = bufB;
#pragma unroll
    for (int stage = 0; stage < 8; stage++) {
        const int s = 1 << stage;
        const int n = 256 >> stage;
        const int m = 128 >> stage;
        __syncthreads();
        for (int w = threadIdx.x; w < NB * 128; w += 256) {
            int t = w >> 7;
            int i = w & 127;
            int p = i >> stage;        // i / s
            int q = i & (s - 1);       // i % s
            float2 a = src[t * TS + q + s * p];
            float2 b = src[t * TS + q + s * (p + m)];
            float2 su = make_float2(a.x + b.x, a.y + b.y);
            float2 df = make_float2(a.x - b.x, a.y - b.y);
            float sn, cs;
            sincospif((INV ? 2.0f : -2.0f) * (float)p / (float)n, &sn, &cs);
            float2 wb = make_float2(df.x * cs - df.y * sn, df.x * sn + df.y * cs);
            dst[t * TS + q + s * (2 * p)]     = su;
            dst[t * TS + q + s * (2 * p + 1)] = wb;
        }
        float2* tm = src; src = dst; dst = tm;
    }
    __syncthreads();
}

// ---------------- Pass 1: forward row FFT of A (along y) ----------------
__global__ __launch_bounds__(256) void k_fwd_rows_A(const float* __restrict__ A) {
    __shared__ float2 bufA[2 * 256];
    __shared__ float2 bufB[2 * 256];
    int b = blockIdx.x;            // 3*128
    int c = b >> 7;
    int pr = b & 127;
    for (int idx = threadIdx.x; idx < 512; idx += 256) {
        int t = idx >> 8, y = idx & 255;
        int x = pr * 2 + t;
        bufA[t * 256 + y] = make_float2(A[(x * 256 + y) * 3 + c], 0.0f);
    }
    fft256<2, 256, false>(bufA, bufB);
    for (int idx = threadIdx.x; idx < 512; idx += 256) {
        int t = idx >> 8, y = idx & 255;
        int x = pr * 2 + t;
        g_fA[(c * 256 + x) * 256 + y] = bufA[t * 256 + y];
    }
}

// ---------------- Pass 2: forward column FFT of A (along x) ----------------
__global__ __launch_bounds__(256) void k_fwd_cols_A() {
    const int TS = 264;
    __shared__ float2 bufA[8 * 264];
    __shared__ float2 bufB[8 * 264];
    int b = blockIdx.x;            // 3*32
    int c = b >> 5;
    int y0 = (b & 31) * 8;
    float2* base = g_fA + c * NPIX;
    for (int idx = threadIdx.x; idx < 2048; idx += 256) {
        int x = idx >> 3, j = idx & 7;
        bufA[j * TS + x] = base[x * 256 + y0 + j];
    }
    fft256<8, 264, false>(bufA, bufB);
    for (int idx = threadIdx.x; idx < 2048; idx += 256) {
        int x = idx >> 3, j = idx & 7;
        base[x * 256 + y0 + j] = bufA[j * TS + x];
    }
}

// ------- Pass 3: H_k = fK_k * fA_{k%3}, inverse row FFT (along y) -------
__global__ __launch_bounds__(256) void k_inv_rows_H(const float* __restrict__ fKr,
                                                    const float* __restrict__ fKi) {
    __shared__ float2 bufA[2 * 256];
    __shared__ float2 bufB[2 * 256];
    int b = blockIdx.x;            // 15*128
    int k = b >> 7;
    int pr = b & 127;
    int c = k - (k / 3) * 3;
    for (int idx = threadIdx.x; idx < 512; idx += 256) {
        int t = idx >> 8, y = idx & 255;
        int x = pr * 2 + t;
        int gi = (x * 256 + y) * 15 + k;
        float2 fk = make_float2(fKr[gi], fKi[gi]);
        bufA[t * 256 + y] = cmulf(fk, g_fA[(c * 256 + x) * 256 + y]);
    }
    fft256<2, 256, true>(bufA, bufB);
    for (int idx = threadIdx.x; idx < 512; idx += 256) {
        int t = idx >> 8, y = idx & 255;
        int x = pr * 2 + t;
        g_tmp[(k * 256 + x) * 256 + y] = bufA[t * 256 + y];
    }
}

// ---- Pass 4: inverse column FFT (along x), scale, growth, * P -> g_G ----
__global__ __launch_bounds__(256) void k_inv_cols_G(const float* __restrict__ P,
                                                    const float* __restrict__ m,
                                                    const float* __restrict__ s) {
    const int TS = 264;
    __shared__ float2 bufA[8 * 264];
    __shared__ float2 bufB[8 * 264];
    int b = blockIdx.x;            // 15*32
    int k = b >> 5;
    int y0 = (b & 31) * 8;
    float2* base = g_tmp + k * NPIX;
    for (int idx = threadIdx.x; idx < 2048; idx += 256) {
        int x = idx >> 3, j = idx & 7;
        bufA[j * TS + x] = base[x * 256 + y0 + j];
    }
    fft256<8, 264, true>(bufA, bufB);
    float mk = m[k];
    float sk = s[k];
    float inv2s2 = 1.0f / (2.0f * sk * sk);
    for (int idx = threadIdx.x; idx < 2048; idx += 256) {
        int x = idx >> 3, j = idx & 7;
        int y = y0 + j;
        float u = bufA[j * TS + x].x * (1.0f / 65536.0f);
        float t = u - mk;
        float g = 2.0f * expf(-t * t * inv2s2) - 1.0f;
        g_G[k * NPIX + x * 256 + y] = g * P[(x * 256 + y) * 15 + k];
    }
}

// ---- Pass 5: channel reduction Uc + Asum per pixel ----
__global__ __launch_bounds__(256) void k_ucas(const float* __restrict__ A) {
    int i = blockIdx.x * 256 + threadIdx.x;
    float u[3] = {0.f, 0.f, 0.f};
#pragma unroll
    for (int k = 0; k < 15; k++) u[k % 3] += g_G[k * NPIX + i];
    float asum = A[i * 3 + 0] + A[i * 3 + 1] + A[i * 3 + 2];
    g_UcAs[i] = make_float4(u[0], u[1], u[2], asum);
}

// ---- Pass 6: Sobel, alpha blend, clip, mu ----
__global__ __launch_bounds__(256) void k_sobel_mu(const float* __restrict__ A) {
    const float SIGMA = 0.65f, MAB = 4.35f, DT = 0.2f;
    int i = blockIdx.x * 256 + threadIdx.x;
    int x = i >> 8, y = i & 255;
    float4 S[3][3];
#pragma unroll
    for (int du = 0; du < 3; du++)
#pragma unroll
        for (int dv = 0; dv < 3; dv++) {
            int xx = x + du - 1, yy = y + dv - 1;
            bool ok = (unsigned)xx < 256u && (unsigned)yy < 256u;
            S[du][dv] = ok ? g_UcAs[xx * 256 + yy] : make_float4(0.f, 0.f, 0.f, 0.f);
        }
    // grad_y (axis 0), grad_x (axis 1); zero-padded SAME, true-convolution Sobel
    float gy[4], gx[4];
    {
        float4 b0 = S[2][0], b1 = S[2][1], b2 = S[2][2];
        float4 t0 = S[0][0], t1 = S[0][1], t2 = S[0][2];
        gy[0] = (b0.x + 2.f * b1.x + b2.x) - (t0.x + 2.f * t1.x + t2.x);
        gy[1] = (b0.y + 2.f * b1.y + b2.y) - (t0.y + 2.f * t1.y + t2.y);
        gy[2] = (b0.z + 2.f * b1.z + b2.z) - (t0.z + 2.f * t1.z + t2.z);
        gy[3] = (b0.w + 2.f * b1.w + b2.w) - (t0.w + 2.f * t1.w + t2.w);
        float4 r0 = S[0][2], r1 = S[1][2], r2 = S[2][2];
        float4 l0 = S[0][0], l1 = S[1][0], l2 = S[2][0];
        gx[0] = (r0.x + 2.f * r1.x + r2.x) - (l0.x + 2.f * l1.x + l2.x);
        gx[1] = (r0.y + 2.f * r1.y + r2.y) - (l0.y + 2.f * l1.y + l2.y);
        gx[2] = (r0.z + 2.f * r1.z + r2.z) - (l0.z + 2.f * l1.z + l2.z);
        gx[3] = (r0.w + 2.f * r1.w + r2.w) - (l0.w + 2.f * l1.w + l2.w);
    }
    float pr = (float)x + 0.5f, pc = (float)y + 0.5f;
#pragma unroll
    for (int c = 0; c < 3; c++) {
        float a = A[i * 3 + c];
        float al = fminf(0.25f * a * a, 1.0f);
        float Fy = gy[c] * (1.0f - al) - gy[3] * al;
        float Fx = gx[c] * (1.0f - al) - gx[3] * al;
        Fy = fminf(fmaxf(Fy, -MAB), MAB);
        Fx = fminf(fmaxf(Fx, -MAB), MAB);
        float mur = fminf(fmaxf(pr + DT * Fy, SIGMA), 256.0f - SIGMA);
        float muc = fminf(fmaxf(pc + DT * Fx, SIGMA), 256.0f - SIGMA);
        g_mu[i * 6 + c]     = mur;
        g_mu[i * 6 + 3 + c] = muc;
    }
}

// ---- Pass 7: reintegration gather (25-source window), softmax-mixed P ----
__global__ __launch_bounds__(256) void k_reint(const float* __restrict__ A,
                                               const float* __restrict__ P,
                                               float* __restrict__ outA,
                                               float* __restrict__ outP) {
    const float SIGMA = 0.65f;
    const float INV4S2 = 1.0f / (4.0f * 0.65f * 0.65f);
    __shared__ float s_mu[400 * 6];
    __shared__ float s_A[400 * 3];
    __shared__ float s_P[400 * 15];
    int x0 = blockIdx.y * 16;
    int y0 = blockIdx.x * 16;
    int tid = threadIdx.x;
    for (int cidx = tid; cidx < 400; cidx += 256) {
        int ti = cidx / 20, tj = cidx - ti * 20;
        int gx = x0 + ti - 2, gy = y0 + tj - 2;
        bool ok = (unsigned)gx < 256u && (unsigned)gy < 256u;
        int gi = gx * 256 + gy;
#pragma unroll
        for (int f = 0; f < 6; f++) s_mu[cidx * 6 + f] = ok ? g_mu[gi * 6 + f] : -1.0e4f;
#pragma unroll
        for (int c = 0; c < 3; c++) s_A[cidx * 3 + c] = ok ? A[gi * 3 + c] : 0.0f;
#pragma unroll
        for (int k = 0; k < 15; k++) s_P[cidx * 15 + k] = ok ? P[gi * 15 + k] : 0.0f;
    }
    __syncthreads();

    int li = tid >> 4, lj = tid & 15;
    int x = x0 + li, y = y0 + lj;
    float pr = (float)x + 0.5f, pc = (float)y + 0.5f;
    float accA[3] = {0.f, 0.f, 0.f};
    float num[15];
#pragma unroll
    for (int k = 0; k < 15; k++) num[k] = 0.0f;
    float den = 0.0f;

    for (int di = 0; di < 5; di++) {
#pragma unroll
        for (int dj = 0; dj < 5; dj++) {
            int cell = (li + di) * 20 + (lj + dj);
            const float* mu = &s_mu[cell * 6];
            float ssum = 0.0f;
#pragma unroll
            for (int c = 0; c < 3; c++) {
                float szr = 0.5f + SIGMA - fabsf(pr - mu[c]);
                float szc = 0.5f + SIGMA - fabsf(pc - mu[3 + c]);
                float ar = fminf(fmaxf(szr, 0.0f), 1.0f) *
                           fminf(fmaxf(szc, 0.0f), 1.0f) * INV4S2;
                float nA = s_A[cell * 3 + c] * ar;
                accA[c] += nA;
                ssum += nA;
            }
            float e = expf(ssum) - 1.0f;
            den += e;
#pragma unroll
            for (int k = 0; k < 15; k++) num[k] += s_P[cell * 15 + k] * e;
        }
    }
    int gi = x * 256 + y;
#pragma unroll
    for (int c = 0; c < 3; c++) outA[gi * 3 + c] = accA[c];
    float inv = 1.0f / (den + 1e-10f);
#pragma unroll
    for (int k = 0; k < 15; k++) outP[gi * 15 + k] = num[k] * inv;
}

extern "C" void kernel_launch(void* const* d_in, const int* in_sizes, int n_in,
                              void* d_out, int out_size) {
    const float* A   = (const float*)d_in[0];
    const float* P   = (const float*)d_in[1];
    const float* fKr = (const float*)d_in[2];
    const float* fKi = (const float*)d_in[3];
    const float* m   = (const float*)d_in[4];
    const float* s   = (const float*)d_in[5];
    float* outA = (float*)d_out;
    float* outP = (float*)d_out + 256 * 256 * 3;

    k_fwd_rows_A<<<3 * 128, 256>>>(A);
    k_fwd_cols_A<<<3 * 32, 256>>>();
    k_inv_rows_H<<<15 * 128, 256>>>(fKr, fKi);
    k_inv_cols_G<<<15 * 32, 256>>>(P, m, s);
    k_ucas<<<256, 256>>>(A);
    k_sobel_mu<<<256, 256>>>(A);
    k_reint<<<dim3(16, 16), 256>>>(A, P, outA, outP);
}

// round 2
// speedup vs baseline: 1.1377x; 1.1377x over previous
#include <cuda_runtime.h>

// FlowLenia single step. SX=SY=256, C=3, K=15, DD=5, DT=0.2, SIGMA=0.65
// Output: newA (256*256*3) followed by newP (256*256*15), float32.
//
// R2: Hermitian pairing (15 inverse planes -> 8, 3 forward -> 2),
//     radix-4 Stockham (4 stages), shared twiddle table (no per-butterfly MUFU).

#define NPIX 65536
static __device__ float2 g_F[2 * NPIX];     // forward FFT planes: F0=fft(A0+i*A1), F1=fft(A2)
static __device__ float2 g_tmp[8 * NPIX];   // paired spectral workspace
static __device__ float  g_G[15 * NPIX];    // growth(U)*P, [k][x][y]
static __device__ float4 g_UcAs[NPIX];      // (Uc0,Uc1,Uc2,Asum) per pixel
static __device__ float  g_mu[NPIX * 6];    // mu per pixel: [row_c0..2, col_c0..2]

__device__ __forceinline__ float2 cmulf(float2 a, float2 b) {
    return make_float2(a.x * b.x - a.y * b.y, a.x * b.y + a.y * b.x);
}

// Build W[j] = exp(-2*pi*i*j/256) (forward sign). 256 threads, one entry each.
__device__ __forceinline__ void fill_W(float2* W) {
    int j = threadIdx.x;
    float sn, cs;
    sincospif(-(float)j * (1.0f / 128.0f), &sn, &cs);
    W[j] = make_float2(cs, sn);
}

// Radix-4 Stockham, 256-point, NB transforms per 256-thread block.
// TS = shared stride per transform. Result back in bufA, natural order.
template <int NB, int TS, bool INV>
__device__ __forceinline__ void fft256_r4(float2* bufA, float2* bufB, const float2* W) {
    float2* src = bufA;
    float2* dst = bufB;
#pragma unroll
    for (int stage = 0; stage < 4; stage++) {
        const int s = 1 << (2 * stage);   // 1,4,16,64
        const int m = 64 >> (2 * stage);  // 64,16,4,1
        __syncthreads();
#pragma unroll
        for (int w = threadIdx.x; w < NB * 64; w += 256) {
            int t = w >> 6;
            int i = w & 63;
            int p = i >> (2 * stage);
            int q = i & (s - 1);
            const float2* sb = src + t * TS;
            float2 x0 = sb[q + s * p];
            float2 x1 = sb[q + s * (p + m)];
            float2 x2 = sb[q + s * (p + 2 * m)];
            float2 x3 = sb[q + s * (p + 3 * m)];
            float2 e0 = make_float2(x0.x + x2.x, x0.y + x2.y);
            float2 e1 = make_float2(x0.x - x2.x, x0.y - x2.y);
            float2 o0 = make_float2(x1.x + x3.x, x1.y + x3.y);
            float2 o1 = make_float2(x1.x - x3.x, x1.y - x3.y);
            // forward: (-i)*o1 ; inverse: (+i)*o1
            float2 io1 = INV ? make_float2(-o1.y, o1.x) : make_float2(o1.y, -o1.x);
            float2 y0 = make_float2(e0.x + o0.x, e0.y + o0.y);
            float2 y2 = make_float2(e0.x - o0.x, e0.y - o0.y);
            float2 y1 = make_float2(e1.x + io1.x, e1.y + io1.y);
            float2 y3 = make_float2(e1.x - io1.x, e1.y - io1.y);
            int ps = p * s;
            float2 w1 = W[ps];
            float2 w2 = W[2 * ps];
            float2 w3 = W[3 * ps];
            if (INV) { w1.y = -w1.y; w2.y = -w2.y; w3.y = -w3.y; }
            float2* db = dst + t * TS;
            db[q + s * (4 * p + 0)] = y0;
            db[q + s * (4 * p + 1)] = cmulf(y1, w1);
            db[q + s * (4 * p + 2)] = cmulf(y2, w2);
            db[q + s * (4 * p + 3)] = cmulf(y3, w3);
        }
        float2* tm = src; src = dst; dst = tm;
    }
    __syncthreads();
}

// ---- Pass 1: forward row FFT (along y) of 2 packed planes ----
// plane 0 = A0 + i*A1, plane 1 = A2
__global__ __launch_bounds__(256) void k_fwd_rows(const float* __restrict__ A) {
    __shared__ float2 bufA[4 * 256];
    __shared__ float2 bufB[4 * 256];
    __shared__ float2 W[256];
    fill_W(W);
    int b = blockIdx.x;            // 2*64
    int plane = b >> 6;
    int x0 = (b & 63) * 4;
    for (int idx = threadIdx.x; idx < 1024; idx += 256) {
        int t = idx >> 8, y = idx & 255;
        int gi = (x0 + t) * 256 + y;
        float2 v;
        if (plane == 0) v = make_float2(A[gi * 3 + 0], A[gi * 3 + 1]);
        else            v = make_float2(A[gi * 3 + 2], 0.0f);
        bufA[t * 256 + y] = v;
    }
    fft256_r4<4, 256, false>(bufA, bufB, W);
    for (int idx = threadIdx.x; idx < 1024; idx += 256) {
        int t = idx >> 8, y = idx & 255;
        g_F[plane * NPIX + (x0 + t) * 256 + y] = bufA[t * 256 + y];
    }
}

// ---- Pass 2: forward column FFT (along x) of 2 planes ----
__global__ __launch_bounds__(256) void k_fwd_cols() {
    const int TS = 264;
    __shared__ float2 bufA[8 * 264];
    __shared__ float2 bufB[8 * 264];
    __shared__ float2 W[256];
    fill_W(W);
    int b = blockIdx.x;            // 2*32
    int plane = b >> 5;
    int y0 = (b & 31) * 8;
    float2* base = g_F + plane * NPIX;
    for (int idx = threadIdx.x; idx < 2048; idx += 256) {
        int x = idx >> 3, j = idx & 7;
        bufA[j * TS + x] = base[x * 256 + y0 + j];
    }
    fft256_r4<8, 264, false>(bufA, bufB, W);
    for (int idx = threadIdx.x; idx < 2048; idx += 256) {
        int x = idx >> 3, j = idx & 7;
        base[x * 256 + y0 + j] = bufA[j * TS + x];
    }
}

// ---- Pass 3: spectral multiply (Hermitian unpack) + paired inverse row FFT ----
// pair j: Z = H_{2j} + i*H_{2j+1};  H_k = fK_k * fA_{k%3}
__global__ __launch_bounds__(256) void k_inv_rows(const float* __restrict__ fKr,
                                                  const float* __restrict__ fKi) {
    __shared__ float2 bufA[4 * 256];
    __shared__ float2 bufB[4 * 256];
    __shared__ float2 W[256];
    fill_W(W);
    int b = blockIdx.x;            // 8*64
    int j = b >> 6;
    int x0 = (b & 63) * 4;
    int k1 = 2 * j;
    int k2 = 2 * j + 1;            // invalid when j==7
    bool k2v = (j < 7);
    int c1 = k1 % 3;
    int c2 = k2 % 3;
    bool need01 = (c1 < 2) || (k2v && c2 < 2);
    bool need2  = (c1 == 2) || (k2v && c2 == 2);

    for (int idx = threadIdx.x; idx < 1024; idx += 256) {
        int t = idx >> 8, y = idx & 255;
        int x = x0 + t;
        int gi = x * 256 + y;
        float2 fa0 = make_float2(0.f, 0.f), fa1 = fa0, fa2 = fa0;
        if (need01) {
            float2 v = g_F[gi];
            int xr = (256 - x) & 255, yr = (256 - y) & 255;
            float2 r = g_F[xr * 256 + yr];   // F0[-v]
            // conj(F0[-v]) = (r.x, -r.y)
            fa0 = make_float2(0.5f * (v.x + r.x), 0.5f * (v.y - r.y));
            fa1 = make_float2(0.5f * (v.y + r.y), 0.5f * (r.x - v.x));
        }
        if (need2) fa2 = g_F[NPIX + gi];
        float2 fc1 = (c1 == 0) ? fa0 : ((c1 == 1) ? fa1 : fa2);
        float2 fk1 = make_float2(fKr[gi * 15 + k1], fKi[gi * 15 + k1]);
        float2 H1 = cmulf(fk1, fc1);
        float2 H2 = make_float2(0.f, 0.f);
        if (k2v) {
            float2 fc2 = (c2 == 0) ? fa0 : ((c2 == 1) ? fa1 : fa2);
            float2 fk2 = make_float2(fKr[gi * 15 + k2], fKi[gi * 15 + k2]);
            H2 = cmulf(fk2, fc2);
        }
        bufA[t * 256 + y] = make_float2(H1.x - H2.y, H1.y + H2.x);
    }
    fft256_r4<4, 256, true>(bufA, bufB, W);
    for (int idx = threadIdx.x; idx < 1024; idx += 256) {
        int t = idx >> 8, y = idx & 255;
        g_tmp[j * NPIX + (x0 + t) * 256 + y] = bufA[t * 256 + y];
    }
}

// ---- Pass 4: paired inverse column FFT + growth + *P -> g_G[k1], g_G[k2] ----
__global__ __launch_bounds__(256) void k_inv_cols(const float* __restrict__ P,
                                                   const float* __restrict__ m,
                                                   const float* __restrict__ s) {
    const int TS = 264;
    __shared__ float2 bufA[8 * 264];
    __shared__ float2 bufB[8 * 264];
    __shared__ float2 W[256];
    fill_W(W);
    int b = blockIdx.x;            // 8*32
    int j = b >> 5;
    int y0 = (b & 31) * 8;
    int k1 = 2 * j, k2 = 2 * j + 1;
    bool k2v = (j < 7);
    float2* base = g_tmp + j * NPIX;
    for (int idx = threadIdx.x; idx < 2048; idx += 256) {
        int x = idx >> 3, jj = idx & 7;
        bufA[jj * TS + x] = base[x * 256 + y0 + jj];
    }
    fft256_r4<8, 264, true>(bufA, bufB, W);
    float m1 = m[k1], s1 = s[k1];
    float i2s1 = 1.0f / (2.0f * s1 * s1);
    float m2 = k2v ? m[k2] : 0.f, s2 = k2v ? s[k2] : 1.f;
    float i2s2 = 1.0f / (2.0f * s2 * s2);
    for (int idx = threadIdx.x; idx < 2048; idx += 256) {
        int x = idx >> 3, jj = idx & 7;
        int y = y0 + jj;
        int gi = x * 256 + y;
        float2 z = bufA[jj * TS + x];
        float u1 = z.x * (1.0f / 65536.0f);
        float t1 = u1 - m1;
        float g1 = 2.0f * expf(-t1 * t1 * i2s1) - 1.0f;
        g_G[k1 * NPIX + gi] = g1 * P[gi * 15 + k1];
        if (k2v) {
            float u2 = z.y * (1.0f / 65536.0f);
            float t2 = u2 - m2;
            float g2 = 2.0f * expf(-t2 * t2 * i2s2) - 1.0f;
            g_G[k2 * NPIX + gi] = g2 * P[gi * 15 + k2];
        }
    }
}

// ---- Pass 5: channel reduction Uc + Asum per pixel ----
__global__ __launch_bounds__(256) void k_ucas(const float* __restrict__ A) {
    int i = blockIdx.x * 256 + threadIdx.x;
    float u[3] = {0.f, 0.f, 0.f};
#pragma unroll
    for (int k = 0; k < 15; k++) u[k % 3] += g_G[k * NPIX + i];
    float asum = A[i * 3 + 0] + A[i * 3 + 1] + A[i * 3 + 2];
    g_UcAs[i] = make_float4(u[0], u[1], u[2], asum);
}

// ---- Pass 6: Sobel, alpha blend, clip, mu ----
__global__ __launch_bounds__(256) void k_sobel_mu(const float* __restrict__ A) {
    const float SIGMA = 0.65f, MAB = 4.35f, DT = 0.2f;
    int i = blockIdx.x * 256 + threadIdx.x;
    int x = i >> 8, y = i & 255;
    float4 S[3][3];
#pragma unroll
    for (int du = 0; du < 3; du++)
#pragma unroll
        for (int dv = 0; dv < 3; dv++) {
            int xx = x + du - 1, yy = y + dv - 1;
            bool ok = (unsigned)xx < 256u && (unsigned)yy < 256u;
            S[du][dv] = ok ? g_UcAs[xx * 256 + yy] : make_float4(0.f, 0.f, 0.f, 0.f);
        }
    float gy[4], gx[4];
    {
        float4 b0 = S[2][0], b1 = S[2][1], b2 = S[2][2];
        float4 t0 = S[0][0], t1 = S[0][1], t2 = S[0][2];
        gy[0] = (b0.x + 2.f * b1.x + b2.x) - (t0.x + 2.f * t1.x + t2.x);
        gy[1] = (b0.y + 2.f * b1.y + b2.y) - (t0.y + 2.f * t1.y + t2.y);
        gy[2] = (b0.z + 2.f * b1.z + b2.z) - (t0.z + 2.f * t1.z + t2.z);
        gy[3] = (b0.w + 2.f * b1.w + b2.w) - (t0.w + 2.f * t1.w + t2.w);
        float4 r0 = S[0][2], r1 = S[1][2], r2 = S[2][2];
        float4 l0 = S[0][0], l1 = S[1][0], l2 = S[2][0];
        gx[0] = (r0.x + 2.f * r1.x + r2.x) - (l0.x + 2.f * l1.x + l2.x);
        gx[1] = (r0.y + 2.f * r1.y + r2.y) - (l0.y + 2.f * l1.y + l2.y);
        gx[2] = (r0.z + 2.f * r1.z + r2.z) - (l0.z + 2.f * l1.z + l2.z);
        gx[3] = (r0.w + 2.f * r1.w + r2.w) - (l0.w + 2.f * l1.w + l2.w);
    }
    float pr = (float)x + 0.5f, pc = (float)y + 0.5f;
#pragma unroll
    for (int c = 0; c < 3; c++) {
        float a = A[i * 3 + c];
        float al = fminf(0.25f * a * a, 1.0f);
        float Fy = gy[c] * (1.0f - al) - gy[3] * al;
        float Fx = gx[c] * (1.0f - al) - gx[3] * al;
        Fy = fminf(fmaxf(Fy, -MAB), MAB);
        Fx = fminf(fmaxf(Fx, -MAB), MAB);
        float mur = fminf(fmaxf(pr + DT * Fy, SIGMA), 256.0f - SIGMA);
        float muc = fminf(fmaxf(pc + DT * Fx, SIGMA), 256.0f - SIGMA);
        g_mu[i * 6 + c]     = mur;
        g_mu[i * 6 + 3 + c] = muc;
    }
}

// ---- Pass 7: reintegration gather (25-source window), softmax-mixed P ----
__global__ __launch_bounds__(256) void k_reint(const float* __restrict__ A,
                                               const float* __restrict__ P,
                                               float* __restrict__ outA,
                                               float* __restrict__ outP) {
    const float SIGMA = 0.65f;
    const float INV4S2 = 1.0f / (4.0f * 0.65f * 0.65f);
    __shared__ float s_mu[400 * 6];
    __shared__ float s_A[400 * 3];
    __shared__ float s_P[400 * 15];
    int x0 = blockIdx.y * 16;
    int y0 = blockIdx.x * 16;
    int tid = threadIdx.x;
    for (int cidx = tid; cidx < 400; cidx += 256) {
        int ti = cidx / 20, tj = cidx - ti * 20;
        int gx = x0 + ti - 2, gy = y0 + tj - 2;
        bool ok = (unsigned)gx < 256u && (unsigned)gy < 256u;
        int gi = gx * 256 + gy;
#pragma unroll
        for (int f = 0; f < 6; f++) s_mu[cidx * 6 + f] = ok ? g_mu[gi * 6 + f] : -1.0e4f;
#pragma unroll
        for (int c = 0; c < 3; c++) s_A[cidx * 3 + c] = ok ? A[gi * 3 + c] : 0.0f;
#pragma unroll
        for (int k = 0; k < 15; k++) s_P[cidx * 15 + k] = ok ? P[gi * 15 + k] : 0.0f;
    }
    __syncthreads();

    int li = tid >> 4, lj = tid & 15;
    int x = x0 + li, y = y0 + lj;
    float pr = (float)x + 0.5f, pc = (float)y + 0.5f;
    float accA[3] = {0.f, 0.f, 0.f};
    float num[15];
#pragma unroll
    for (int k = 0; k < 15; k++) num[k] = 0.0f;
    float den = 0.0f;

    for (int di = 0; di < 5; di++) {
#pragma unroll
        for (int dj = 0; dj < 5; dj++) {
            int cell = (li + di) * 20 + (lj + dj);
            const float* mu = &s_mu[cell * 6];
            float ssum = 0.0f;
#pragma unroll
            for (int c = 0; c < 3; c++) {
                float szr = 0.5f + SIGMA - fabsf(pr - mu[c]);
                float szc = 0.5f + SIGMA - fabsf(pc - mu[3 + c]);
                float ar = fminf(fmaxf(szr, 0.0f), 1.0f) *
                           fminf(fmaxf(szc, 0.0f), 1.0f) * INV4S2;
                float nA = s_A[cell * 3 + c] * ar;
                accA[c] += nA;
                ssum += nA;
            }
            float e = expf(ssum) - 1.0f;
            den += e;
#pragma unroll
            for (int k = 0; k < 15; k++) num[k] += s_P[cell * 15 + k] * e;
        }
    }
    int gi = x * 256 + y;
#pragma unroll
    for (int c = 0; c < 3; c++) outA[gi * 3 + c] = accA[c];
    float inv = 1.0f / (den + 1e-10f);
#pragma unroll
    for (int k = 0; k < 15; k++) outP[gi * 15 + k] = num[k] * inv;
}

extern "C" void kernel_launch(void* const* d_in, const int* in_sizes, int n_in,
                              void* d_out, int out_size) {
    const float* A   = (const float*)d_in[0];
    const float* P   = (const float*)d_in[1];
    const float* fKr = (const float*)d_in[2];
    const float* fKi = (const float*)d_in[3];
    const float* m   = (const float*)d_in[4];
    const float* s   = (const float*)d_in[5];
    float* outA = (float*)d_out;
    float* outP = (float*)d_out + 256 * 256 * 3;

    k_fwd_rows<<<2 * 64, 256>>>(A);
    k_fwd_cols<<<2 * 32, 256>>>();
    k_inv_rows<<<8 * 64, 256>>>(fKr, fKi);
    k_inv_cols<<<8 * 32, 256>>>(P, m, s);
    k_ucas<<<256, 256>>>(A);
    k_sobel_mu<<<256, 256>>>(A);
    k_reint<<<dim3(16, 16), 256>>>(A, P, outA, outP);
}

// round 3
// speedup vs baseline: 1.1504x; 1.0111x over previous
#include <cuda_runtime.h>

// FlowLenia single step. SX=SY=256, C=3, K=15, DD=5, DT=0.2, SIGMA=0.65
// Output: newA (256*256*3) followed by newP (256*256*15), float32.
//
// R3: warp-level 256-pt FFT (8 regs x 32 lanes, shuffle-based, barrier-free
//     row passes, 3-barrier column passes), P-multiply moved to k_ucas.

#define NPIX 65536
static __device__ float2 g_F[2 * NPIX];     // F0=fft(A0+i*A1), F1=fft(A2)
static __device__ float2 g_tmp[8 * NPIX];   // paired spectral workspace
static __device__ float  g_G[15 * NPIX];    // growth(U) only, [k][x][y]
static __device__ float4 g_UcAs[NPIX];      // (Uc0,Uc1,Uc2,Asum)
static __device__ float  g_mu[NPIX * 6];    // [row_c0..2, col_c0..2]

__device__ __forceinline__ float2 cmulf(float2 a, float2 b) {
    return make_float2(a.x * b.x - a.y * b.y, a.x * b.y + a.y * b.x);
}
__device__ __forceinline__ float2 cadd(float2 a, float2 b) {
    return make_float2(a.x + b.x, a.y + b.y);
}
__device__ __forceinline__ float2 csub(float2 a, float2 b) {
    return make_float2(a.x - b.x, a.y - b.y);
}
__device__ __forceinline__ int brev5(int l) {
    return ((l & 1) << 4) | ((l & 2) << 2) | (l & 4) | ((l & 8) >> 2) | ((l & 16) >> 4);
}
__device__ __forceinline__ constexpr int brev3(int q) {
    return ((q & 1) << 2) | (q & 2) | ((q & 4) >> 2);
}

// Warp-collective 256-pt FFT. Input: v[r] = x[l + 32*r] (l = lane).
// Output: lane l, reg q holds X[brev3(q) + 8*brev5(l)].
// Forward: W = exp(-2*pi*i/N). INV=true: conjugate (no 1/N scale).
template <bool INV>
__device__ __forceinline__ void warp_fft256(float2 v[8]) {
    const float SGN = INV ? 1.0f : -1.0f;
    const float RH = 0.70710678118654752f;
    int l = threadIdx.x & 31;
    // Step A: 8-pt DIF over registers (twiddles W_8)
    {
        float2 t;
        t = csub(v[0], v[4]); v[0] = cadd(v[0], v[4]); v[4] = t;
        t = csub(v[1], v[5]); v[1] = cadd(v[1], v[5]);
        v[5] = cmulf(t, make_float2(RH, SGN * RH));
        t = csub(v[2], v[6]); v[2] = cadd(v[2], v[6]);
        v[6] = make_float2(-SGN * t.y, SGN * t.x);
        t = csub(v[3], v[7]); v[3] = cadd(v[3], v[7]);
        v[7] = cmulf(t, make_float2(-RH, SGN * RH));
    }
    {
        float2 t;
        t = csub(v[0], v[2]); v[0] = cadd(v[0], v[2]); v[2] = t;
        t = csub(v[1], v[3]); v[1] = cadd(v[1], v[3]);
        v[3] = make_float2(-SGN * t.y, SGN * t.x);
        t = csub(v[4], v[6]); v[4] = cadd(v[4], v[6]); v[6] = t;
        t = csub(v[5], v[7]); v[5] = cadd(v[5], v[7]);
        v[7] = make_float2(-SGN * t.y, SGN * t.x);
    }
    {
        float2 t;
        t = csub(v[0], v[1]); v[0] = cadd(v[0], v[1]); v[1] = t;
        t = csub(v[2], v[3]); v[2] = cadd(v[2], v[3]); v[3] = t;
        t = csub(v[4], v[5]); v[4] = cadd(v[4], v[5]); v[5] = t;
        t = csub(v[6], v[7]); v[6] = cadd(v[6], v[7]); v[7] = t;
    }
    // Step B: middle twiddle W_256^{l * brev3(q)}
    {
        float sn, cs;
        sincospif(SGN * (float)l * (1.0f / 128.0f), &sn, &cs);
        float2 w1 = make_float2(cs, sn);
        float2 w2 = cmulf(w1, w1);
        float2 w4 = cmulf(w2, w2);
        float2 w3 = cmulf(w1, w2);
        float2 w5 = cmulf(w1, w4);
        float2 w6 = cmulf(w2, w4);
        float2 w7 = cmulf(w3, w4);
        v[1] = cmulf(v[1], w4);  // brev3(1)=4
        v[2] = cmulf(v[2], w2);  // 2
        v[3] = cmulf(v[3], w6);  // 6
        v[4] = cmulf(v[4], w1);  // 1
        v[5] = cmulf(v[5], w5);  // 5
        v[6] = cmulf(v[6], w3);  // 3
        v[7] = cmulf(v[7], w7);  // 7
    }
    // Step C: 32-pt DIF across lanes via shuffles
#pragma unroll
    for (int s5 = 0; s5 < 5; s5++) {
        int h = 16 >> s5;
        int e = (l & (h - 1)) << s5;
        float sn, cs;
        sincospif(SGN * (float)e * (1.0f / 16.0f), &sn, &cs);
        float2 tw = make_float2(cs, sn);
        bool up = (l & h) != 0;
#pragma unroll
        for (int q = 0; q < 8; q++) {
            float2 p;
            p.x = __shfl_xor_sync(0xffffffffu, v[q].x, h);
            p.y = __shfl_xor_sync(0xffffffffu, v[q].y, h);
            if (up) v[q] = cmulf(csub(p, v[q]), tw);
            else    v[q] = cadd(v[q], p);
        }
    }
}

// ---- Pass 1: forward row FFT (along y). plane0 = A0+i*A1, plane1 = A2 ----
__global__ __launch_bounds__(64) void k_fwd_rows(const float* __restrict__ A) {
    int wid = blockIdx.x * 2 + (threadIdx.x >> 5);
    int l = threadIdx.x & 31;
    int plane = wid >> 8;
    int x = wid & 255;
    float2 v[8];
#pragma unroll
    for (int r = 0; r < 8; r++) {
        int y = l + 32 * r;
        int gi = (x * 256 + y) * 3;
        v[r] = (plane == 0) ? make_float2(A[gi], A[gi + 1])
                            : make_float2(A[gi + 2], 0.0f);
    }
    warp_fft256<false>(v);
    int kl = 8 * brev5(l);
    float2* out = g_F + plane * NPIX + x * 256;
#pragma unroll
    for (int q = 0; q < 8; q++) out[kl + brev3(q)] = v[q];
}

// ---- Pass 2: forward column FFT (along x), 4 columns per 128-thr block ----
__global__ __launch_bounds__(128) void k_fwd_cols() {
    __shared__ float2 sbuf[1090];
    int b = blockIdx.x;            // 2*64
    int plane = b >> 6;
    int y0 = (b & 63) * 4;
    float2* base = g_F + plane * NPIX;
    int tid = threadIdx.x;
    for (int i = tid; i < 1024; i += 128) {
        int x = i >> 2, jj = i & 3;
        sbuf[jj * 264 + x] = base[x * 256 + y0 + jj];
    }
    __syncthreads();
    int w = tid >> 5, l = tid & 31;
    float2 v[8];
#pragma unroll
    for (int r = 0; r < 8; r++) v[r] = sbuf[w * 264 + l + 32 * r];
    warp_fft256<false>(v);
    __syncthreads();
    int kl = 8 * brev5(l);
#pragma unroll
    for (int q = 0; q < 8; q++) {
        int k = kl + brev3(q);
        sbuf[w * 273 + k + (k >> 4)] = v[q];
    }
    __syncthreads();
    for (int i = tid; i < 1024; i += 128) {
        int x = i >> 2, jj = i & 3;
        base[x * 256 + y0 + jj] = sbuf[jj * 273 + x + (x >> 4)];
    }
}

// ---- Pass 3: Hermitian unpack + spectral multiply + inverse row FFT ----
__global__ __launch_bounds__(64) void k_inv_rows(const float* __restrict__ fKr,
                                                 const float* __restrict__ fKi) {
    int wid = blockIdx.x * 2 + (threadIdx.x >> 5);
    int l = threadIdx.x & 31;
    int j = wid >> 8;              // 0..7
    int x = wid & 255;
    int k1 = 2 * j, k2 = 2 * j + 1;
    bool k2v = (j < 7);
    int c1 = k1 % 3, c2 = k2 % 3;
    bool need2 = (c1 == 2) || (k2v && c2 == 2);
    int xr = (256 - x) & 255;
    float2 v[8];
#pragma unroll
    for (int r = 0; r < 8; r++) {
        int y = l + 32 * r;
        int gi = x * 256 + y;
        int yr = (256 - y) & 255;
        float2 fv = g_F[gi];
        float2 fr = g_F[xr * 256 + yr];
        float2 fa0 = make_float2(0.5f * (fv.x + fr.x), 0.5f * (fv.y - fr.y));
        float2 fa1 = make_float2(0.5f * (fv.y + fr.y), 0.5f * (fr.x - fv.x));
        float2 fa2 = need2 ? g_F[NPIX + gi] : make_float2(0.f, 0.f);
        float2 fc1 = (c1 == 0) ? fa0 : ((c1 == 1) ? fa1 : fa2);
        float2 H1 = cmulf(make_float2(fKr[gi * 15 + k1], fKi[gi * 15 + k1]), fc1);
        float2 H2 = make_float2(0.f, 0.f);
        if (k2v) {
            float2 fc2 = (c2 == 0) ? fa0 : ((c2 == 1) ? fa1 : fa2);
            H2 = cmulf(make_float2(fKr[gi * 15 + k2], fKi[gi * 15 + k2]), fc2);
        }
        v[r] = make_float2(H1.x - H2.y, H1.y + H2.x);
    }
    warp_fft256<true>(v);
    int kl = 8 * brev5(l);
    float2* out = g_tmp + j * NPIX + x * 256;
#pragma unroll
    for (int q = 0; q < 8; q++) out[kl + brev3(q)] = v[q];
}

// ---- Pass 4: inverse column FFT + growth -> g_G[k1], g_G[k2] ----
__global__ __launch_bounds__(128) void k_inv_cols(const float* __restrict__ m,
                                                  const float* __restrict__ s) {
    __shared__ float2 sbuf[1090];
    int b = blockIdx.x;            // 8*64
    int j = b >> 6;
    int y0 = (b & 63) * 4;
    int k1 = 2 * j, k2 = 2 * j + 1;
    bool k2v = (j < 7);
    float2* base = g_tmp + j * NPIX;
    int tid = threadIdx.x;
    for (int i = tid; i < 1024; i += 128) {
        int x = i >> 2, jj = i & 3;
        sbuf[jj * 264 + x] = base[x * 256 + y0 + jj];
    }
    __syncthreads();
    int w = tid >> 5, l = tid & 31;
    float2 v[8];
#pragma unroll
    for (int r = 0; r < 8; r++) v[r] = sbuf[w * 264 + l + 32 * r];
    warp_fft256<true>(v);
    float m1 = m[k1], s1 = s[k1];
    float i2s1 = 1.0f / (2.0f * s1 * s1);
    float m2 = k2v ? m[k2] : 0.f, s2 = k2v ? s[k2] : 1.f;
    float i2s2 = 1.0f / (2.0f * s2 * s2);
    __syncthreads();
    int kl = 8 * brev5(l);
#pragma unroll
    for (int q = 0; q < 8; q++) {
        int k = kl + brev3(q);
        float u1 = v[q].x * (1.0f / 65536.0f);
        float t1 = u1 - m1;
        float g1 = 2.0f * expf(-t1 * t1 * i2s1) - 1.0f;
        float u2 = v[q].y * (1.0f / 65536.0f);
        float t2 = u2 - m2;
        float g2 = 2.0f * expf(-t2 * t2 * i2s2) - 1.0f;
        sbuf[w * 273 + k + (k >> 4)] = make_float2(g1, g2);
    }
    __syncthreads();
    for (int i = tid; i < 1024; i += 128) {
        int x = i >> 2, jj = i & 3;
        float2 val = sbuf[jj * 273 + x + (x >> 4)];
        int gi = x * 256 + y0 + jj;
        g_G[k1 * NPIX + gi] = val.x;
        if (k2v) g_G[k2 * NPIX + gi] = val.y;
    }
}

// ---- Pass 5: channel reduction Uc = sum_k growth*P + Asum ----
__global__ __launch_bounds__(256) void k_ucas(const float* __restrict__ A,
                                              const float* __restrict__ P) {
    int i = blockIdx.x * 256 + threadIdx.x;
    float u[3] = {0.f, 0.f, 0.f};
#pragma unroll
    for (int k = 0; k < 15; k++) u[k % 3] += g_G[k * NPIX + i] * P[i * 15 + k];
    float asum = A[i * 3 + 0] + A[i * 3 + 1] + A[i * 3 + 2];
    g_UcAs[i] = make_float4(u[0], u[1], u[2], asum);
}

// ---- Pass 6: Sobel, alpha blend, clip, mu ----
__global__ __launch_bounds__(256) void k_sobel_mu(const float* __restrict__ A) {
    const float SIGMA = 0.65f, MAB = 4.35f, DT = 0.2f;
    int i = blockIdx.x * 256 + threadIdx.x;
    int x = i >> 8, y = i & 255;
    float4 S[3][3];
#pragma unroll
    for (int du = 0; du < 3; du++)
#pragma unroll
        for (int dv = 0; dv < 3; dv++) {
            int xx = x + du - 1, yy = y + dv - 1;
            bool ok = (unsigned)xx < 256u && (unsigned)yy < 256u;
            S[du][dv] = ok ? g_UcAs[xx * 256 + yy] : make_float4(0.f, 0.f, 0.f, 0.f);
        }
    float gy[4], gx[4];
    {
        float4 b0 = S[2][0], b1 = S[2][1], b2 = S[2][2];
        float4 t0 = S[0][0], t1 = S[0][1], t2 = S[0][2];
        gy[0] = (b0.x + 2.f * b1.x + b2.x) - (t0.x + 2.f * t1.x + t2.x);
        gy[1] = (b0.y + 2.f * b1.y + b2.y) - (t0.y + 2.f * t1.y + t2.y);
        gy[2] = (b0.z + 2.f * b1.z + b2.z) - (t0.z + 2.f * t1.z + t2.z);
        gy[3] = (b0.w + 2.f * b1.w + b2.w) - (t0.w + 2.f * t1.w + t2.w);
        float4 r0 = S[0][2], r1 = S[1][2], r2 = S[2][2];
        float4 l0 = S[0][0], l1 = S[1][0], l2 = S[2][0];
        gx[0] = (r0.x + 2.f * r1.x + r2.x) - (l0.x + 2.f * l1.x + l2.x);
        gx[1] = (r0.y + 2.f * r1.y + r2.y) - (l0.y + 2.f * l1.y + l2.y);
        gx[2] = (r0.z + 2.f * r1.z + r2.z) - (l0.z + 2.f * l1.z + l2.z);
        gx[3] = (r0.w + 2.f * r1.w + r2.w) - (l0.w + 2.f * l1.w + l2.w);
    }
    float pr = (float)x + 0.5f, pc = (float)y + 0.5f;
#pragma unroll
    for (int c = 0; c < 3; c++) {
        float a = A[i * 3 + c];
        float al = fminf(0.25f * a * a, 1.0f);
        float Fy = gy[c] * (1.0f - al) - gy[3] * al;
        float Fx = gx[c] * (1.0f - al) - gx[3] * al;
        Fy = fminf(fmaxf(Fy, -MAB), MAB);
        Fx = fminf(fmaxf(Fx, -MAB), MAB);
        float mur = fminf(fmaxf(pr + DT * Fy, SIGMA), 256.0f - SIGMA);
        float muc = fminf(fmaxf(pc + DT * Fx, SIGMA), 256.0f - SIGMA);
        g_mu[i * 6 + c]     = mur;
        g_mu[i * 6 + 3 + c] = muc;
    }
}

// ---- Pass 7: reintegration gather (25-source window), softmax-mixed P ----
__global__ __launch_bounds__(256) void k_reint(const float* __restrict__ A,
                                               const float* __restrict__ P,
                                               float* __restrict__ outA,
                                               float* __restrict__ outP) {
    const float SIGMA = 0.65f;
    const float INV4S2 = 1.0f / (4.0f * 0.65f * 0.65f);
    __shared__ float s_mu[400 * 6];
    __shared__ float s_A[400 * 3];
    __shared__ float s_P[400 * 15];
    int x0 = blockIdx.y * 16;
    int y0 = blockIdx.x * 16;
    int tid = threadIdx.x;
    for (int cidx = tid; cidx < 400; cidx += 256) {
        int ti = cidx / 20, tj = cidx - ti * 20;
        int gx = x0 + ti - 2, gy = y0 + tj - 2;
        bool ok = (unsigned)gx < 256u && (unsigned)gy < 256u;
        int gi = gx * 256 + gy;
#pragma unroll
        for (int f = 0; f < 6; f++) s_mu[cidx * 6 + f] = ok ? g_mu[gi * 6 + f] : -1.0e4f;
#pragma unroll
        for (int c = 0; c < 3; c++) s_A[cidx * 3 + c] = ok ? A[gi * 3 + c] : 0.0f;
#pragma unroll
        for (int k = 0; k < 15; k++) s_P[cidx * 15 + k] = ok ? P[gi * 15 + k] : 0.0f;
    }
    __syncthreads();

    int li = tid >> 4, lj = tid & 15;
    int x = x0 + li, y = y0 + lj;
    float pr = (float)x + 0.5f, pc = (float)y + 0.5f;
    float accA[3] = {0.f, 0.f, 0.f};
    float num[15];
#pragma unroll
    for (int k = 0; k < 15; k++) num[k] = 0.0f;
    float den = 0.0f;

    for (int di = 0; di < 5; di++) {
#pragma unroll
        for (int dj = 0; dj < 5; dj++) {
            int cell = (li + di) * 20 + (lj + dj);
            const float* mu = &s_mu[cell * 6];
            float ssum = 0.0f;
#pragma unroll
            for (int c = 0; c < 3; c++) {
                float szr = 0.5f + SIGMA - fabsf(pr - mu[c]);
                float szc = 0.5f + SIGMA - fabsf(pc - mu[3 + c]);
                float ar = fminf(fmaxf(szr, 0.0f), 1.0f) *
                           fminf(fmaxf(szc, 0.0f), 1.0f) * INV4S2;
                float nA = s_A[cell * 3 + c] * ar;
                accA[c] += nA;
                ssum += nA;
            }
            float e = expf(ssum) - 1.0f;
            den += e;
#pragma unroll
            for (int k = 0; k < 15; k++) num[k] += s_P[cell * 15 + k] * e;
        }
    }
    int gi = x * 256 + y;
#pragma unroll
    for (int c = 0; c < 3; c++) outA[gi * 3 + c] = accA[c];
    float inv = 1.0f / (den + 1e-10f);
#pragma unroll
    for (int k = 0; k < 15; k++) outP[gi * 15 + k] = num[k] * inv;
}

extern "C" void kernel_launch(void* const* d_in, const int* in_sizes, int n_in,
                              void* d_out, int out_size) {
    const float* A   = (const float*)d_in[0];
    const float* P   = (const float*)d_in[1];
    const float* fKr = (const float*)d_in[2];
    const float* fKi = (const float*)d_in[3];
    const float* m   = (const float*)d_in[4];
    const float* s   = (const float*)d_in[5];
    float* outA = (float*)d_out;
    float* outP = (float*)d_out + 256 * 256 * 3;

    k_fwd_rows<<<256, 64>>>(A);
    k_fwd_cols<<<128, 128>>>();
    k_inv_rows<<<1024, 64>>>(fKr, fKi);
    k_inv_cols<<<512, 128>>>(m, s);
    k_ucas<<<256, 256>>>(A, P);
    k_sobel_mu<<<256, 256>>>(A);
    k_reint<<<dim3(16, 16), 256>>>(A, P, outA, outP);
}

// round 4
// speedup vs baseline: 1.2443x; 1.0817x over previous
#include <cuda_runtime.h>

// FlowLenia single step. SX=SY=256, C=3, K=15, DD=5, DT=0.2, SIGMA=0.65
// Output: newA (256*256*3) followed by newP (256*256*15), float32.
//
// R4: 2-warp (64-thread) 256-pt FFT groups (4 regs/thread) -> 2x resident
//     warps; k_spec pass for coalesced fK spectral multiply; conflict-free
//     smem pads.

#define NPIX 65536
static __device__ float4 g_F4[NPIX];          // 2 planes of float2
static __device__ float4 g_tmp4[4 * NPIX];    // 8 planes of float2
#define G_F   ((float2*)g_F4)
#define G_TMP ((float2*)g_tmp4)
static __device__ float  g_G[15 * NPIX];      // growth(U), [k][x][y]
static __device__ float4 g_UcAs[NPIX];        // (Uc0,Uc1,Uc2,Asum)
static __device__ float  g_mu[NPIX * 6];      // [row_c0..2, col_c0..2]

__device__ __forceinline__ float2 cmulf(float2 a, float2 b) {
    return make_float2(a.x * b.x - a.y * b.y, a.x * b.y + a.y * b.x);
}
__device__ __forceinline__ float2 cadd(float2 a, float2 b) {
    return make_float2(a.x + b.x, a.y + b.y);
}
__device__ __forceinline__ float2 csub(float2 a, float2 b) {
    return make_float2(a.x - b.x, a.y - b.y);
}
__device__ __forceinline__ int brev5(int l) {
    return ((l & 1) << 4) | ((l & 2) << 2) | (l & 4) | ((l & 8) >> 2) | ((l & 16) >> 4);
}

// 256-pt FFT across a 64-thread group (t = tid&63), v[r] = x[t + 64r].
// Output: thread t, reg q holds X[q + 4*(t>>5) + 8*brev5(t&31)].
// xch: 4*66 float2 scratch per group. Contains ONE block-wide __syncthreads.
template <bool INV>
__device__ __forceinline__ void group_fft256(float2 v[4], float2* xch, int t) {
    const float SGN = INV ? 1.0f : -1.0f;
    int l = t & 31;
    int w = t >> 5;
    // radix-4 DIF over regs: X0..X3 directly
    float2 e0 = cadd(v[0], v[2]);
    float2 e1 = csub(v[0], v[2]);
    float2 o0 = cadd(v[1], v[3]);
    float2 o1 = csub(v[1], v[3]);
    float2 io1 = make_float2(-SGN * o1.y, SGN * o1.x);  // FWD: -i*o1, INV: +i*o1
    v[0] = cadd(e0, o0);
    v[2] = csub(e0, o0);
    v[1] = cadd(e1, io1);
    v[3] = csub(e1, io1);
    // twiddle W256^{t*q}
    float sn, cs;
    sincospif(SGN * (float)t * (1.0f / 128.0f), &sn, &cs);
    float2 w1 = make_float2(cs, sn);
    float2 w2 = cmulf(w1, w1);
    float2 w3 = cmulf(w2, w1);
    v[1] = cmulf(v[1], w1);
    v[2] = cmulf(v[2], w2);
    v[3] = cmulf(v[3], w3);
    // 64-pt stage 1: cross-warp butterfly t <-> t^32 via smem
#pragma unroll
    for (int q = 0; q < 4; q++) xch[q * 66 + t] = v[q];
    __syncthreads();
    {
        int pt = t ^ 32;
        sincospif(SGN * (float)l * (1.0f / 32.0f), &sn, &cs);
        float2 wt = make_float2(cs, sn);
#pragma unroll
        for (int q = 0; q < 4; q++) {
            float2 p = xch[q * 66 + pt];
            if (w == 0) v[q] = cadd(v[q], p);
            else        v[q] = cmulf(csub(p, v[q]), wt);
        }
    }
    // 32-pt across lanes via shuffles
#pragma unroll
    for (int s5 = 0; s5 < 5; s5++) {
        int h = 16 >> s5;
        int e = (l & (h - 1)) << s5;
        sincospif(SGN * (float)e * (1.0f / 16.0f), &sn, &cs);
        float2 tw = make_float2(cs, sn);
        bool up = (l & h) != 0;
#pragma unroll
        for (int q = 0; q < 4; q++) {
            float2 p;
            p.x = __shfl_xor_sync(0xffffffffu, v[q].x, h);
            p.y = __shfl_xor_sync(0xffffffffu, v[q].y, h);
            if (up) v[q] = cmulf(csub(p, v[q]), tw);
            else    v[q] = cadd(v[q], p);
        }
    }
}

__device__ __forceinline__ int out_k0(int t) {
    return ((t >> 5) << 2) + 8 * brev5(t & 31);
}

// ---- Pass 1: forward row FFT (along y). plane0 = A0+i*A1, plane1 = A2 ----
__global__ __launch_bounds__(256) void k_fwd_rows(const float* __restrict__ A) {
    __shared__ float2 xch[4][4 * 66];
    int tid = threadIdx.x;
    int g = tid >> 6, t = tid & 63;
    int gid = blockIdx.x * 4 + g;   // 0..511
    int plane = gid >> 8;
    int x = gid & 255;
    float2 v[4];
#pragma unroll
    for (int r = 0; r < 4; r++) {
        int gi = (x * 256 + t + 64 * r) * 3;
        v[r] = (plane == 0) ? make_float2(A[gi], A[gi + 1])
                            : make_float2(A[gi + 2], 0.0f);
    }
    group_fft256<false>(v, xch[g], t);
    int k0 = out_k0(t);
    float4* out = (float4*)(G_F + plane * NPIX + x * 256 + k0);
    out[0] = make_float4(v[0].x, v[0].y, v[1].x, v[1].y);
    out[1] = make_float4(v[2].x, v[2].y, v[3].x, v[3].y);
}

// ---- Pass 2: forward column FFT (along x), 4 columns per 256-thr block ----
__global__ __launch_bounds__(256) void k_fwd_cols() {
    __shared__ float2 stage[4 * 292];
    __shared__ float2 xch[4][4 * 66];
    int b = blockIdx.x;             // 2*64
    int plane = b >> 6;
    int y0 = (b & 63) * 4;
    float2* base = G_F + plane * NPIX;
    int tid = threadIdx.x;
    for (int i = tid; i < 1024; i += 256)
        stage[(i & 3) * 292 + (i >> 2)] = base[(i >> 2) * 256 + y0 + (i & 3)];
    __syncthreads();
    int g = tid >> 6, t = tid & 63;
    float2 v[4];
#pragma unroll
    for (int r = 0; r < 4; r++) v[r] = stage[g * 292 + t + 64 * r];
    group_fft256<false>(v, xch[g], t);   // internal barrier orders stage reads
    int k0 = out_k0(t);
#pragma unroll
    for (int q = 0; q < 4; q++) {
        int k = k0 + q;
        stage[g * 292 + k + (k >> 3)] = v[q];
    }
    __syncthreads();
    for (int i = tid; i < 1024; i += 256) {
        int x = i >> 2, jj = i & 3;
        base[x * 256 + y0 + jj] = stage[jj * 292 + x + (x >> 3)];
    }
}

// ---- Pass 3: spectral multiply (Hermitian unpack), coalesced fK reads ----
// Z_j = H_{2j} + i*H_{2j+1}, H_k = fK_k * fA_{k%3}. Planar output to g_tmp.
__global__ __launch_bounds__(256) void k_spec(const float* __restrict__ fKr,
                                              const float* __restrict__ fKi) {
    int i = blockIdx.x * 256 + threadIdx.x;
    int x = i >> 8, y = i & 255;
    int xr = (256 - x) & 255, yr = (256 - y) & 255;
    float2 fv = G_F[i];
    float2 fr = G_F[xr * 256 + yr];
    float2 fa[3];
    fa[0] = make_float2(0.5f * (fv.x + fr.x), 0.5f * (fv.y - fr.y));
    fa[1] = make_float2(0.5f * (fv.y + fr.y), 0.5f * (fr.x - fv.x));
    fa[2] = G_F[NPIX + i];
    float kr[15], ki[15];
#pragma unroll
    for (int k = 0; k < 15; k++) { kr[k] = fKr[i * 15 + k]; ki[k] = fKi[i * 15 + k]; }
#pragma unroll
    for (int j = 0; j < 7; j++) {
        int k1 = 2 * j, k2 = 2 * j + 1;
        float2 H1 = cmulf(make_float2(kr[k1], ki[k1]), fa[k1 % 3]);
        float2 H2 = cmulf(make_float2(kr[k2], ki[k2]), fa[k2 % 3]);
        G_TMP[j * NPIX + i] = make_float2(H1.x - H2.y, H1.y + H2.x);
    }
    G_TMP[7 * NPIX + i] = cmulf(make_float2(kr[14], ki[14]), fa[2]);
}

// ---- Pass 4: inverse row FFT (in-place on g_tmp), planar ----
__global__ __launch_bounds__(256) void k_inv_rows() {
    __shared__ float2 xch[4][4 * 66];
    int tid = threadIdx.x;
    int g = tid >> 6, t = tid & 63;
    int gid = blockIdx.x * 4 + g;   // 0..2047
    int j = gid >> 8, x = gid & 255;
    float2* row = G_TMP + j * NPIX + x * 256;
    float2 v[4];
#pragma unroll
    for (int r = 0; r < 4; r++) v[r] = row[t + 64 * r];
    group_fft256<true>(v, xch[g], t);
    int k0 = out_k0(t);
    float4* out = (float4*)(row + k0);
    out[0] = make_float4(v[0].x, v[0].y, v[1].x, v[1].y);
    out[1] = make_float4(v[2].x, v[2].y, v[3].x, v[3].y);
}

// ---- Pass 5: inverse column FFT + growth -> g_G[k1], g_G[k2] ----
__global__ __launch_bounds__(256) void k_inv_cols(const float* __restrict__ m,
                                                  const float* __restrict__ s) {
    __shared__ float2 stage[4 * 292];
    __shared__ float2 xch[4][4 * 66];
    int b = blockIdx.x;             // 8*64
    int j = b >> 6;
    int y0 = (b & 63) * 4;
    int k1 = 2 * j, k2 = 2 * j + 1;
    bool k2v = (j < 7);
    float2* base = G_TMP + j * NPIX;
    int tid = threadIdx.x;
    for (int i = tid; i < 1024; i += 256)
        stage[(i & 3) * 292 + (i >> 2)] = base[(i >> 2) * 256 + y0 + (i & 3)];
    __syncthreads();
    int g = tid >> 6, t = tid & 63;
    float2 v[4];
#pragma unroll
    for (int r = 0; r < 4; r++) v[r] = stage[g * 292 + t + 64 * r];
    group_fft256<true>(v, xch[g], t);
    float m1 = m[k1], s1 = s[k1];
    float i2s1 = 1.0f / (2.0f * s1 * s1);
    float m2 = k2v ? m[k2] : 0.f, s2 = k2v ? s[k2] : 1.f;
    float i2s2 = 1.0f / (2.0f * s2 * s2);
    int k0 = out_k0(t);
#pragma unroll
    for (int q = 0; q < 4; q++) {
        float u1 = v[q].x * (1.0f / 65536.0f);
        float t1 = u1 - m1;
        float g1 = 2.0f * expf(-t1 * t1 * i2s1) - 1.0f;
        float u2 = v[q].y * (1.0f / 65536.0f);
        float t2 = u2 - m2;
        float g2 = 2.0f * expf(-t2 * t2 * i2s2) - 1.0f;
        int k = k0 + q;
        stage[g * 292 + k + (k >> 3)] = make_float2(g1, g2);
    }
    __syncthreads();
    for (int i = tid; i < 1024; i += 256) {
        int x = i >> 2, jj = i & 3;
        float2 val = stage[jj * 292 + x + (x >> 3)];
        int gi = x * 256 + y0 + jj;
        g_G[k1 * NPIX + gi] = val.x;
        if (k2v) g_G[k2 * NPIX + gi] = val.y;
    }
}

// ---- Pass 6: channel reduction Uc = sum_k growth*P + Asum ----
__global__ __launch_bounds__(256) void k_ucas(const float* __restrict__ A,
                                              const float* __restrict__ P) {
    int i = blockIdx.x * 256 + threadIdx.x;
    float u[3] = {0.f, 0.f, 0.f};
#pragma unroll
    for (int k = 0; k < 15; k++) u[k % 3] += g_G[k * NPIX + i] * P[i * 15 + k];
    float asum = A[i * 3 + 0] + A[i * 3 + 1] + A[i * 3 + 2];
    g_UcAs[i] = make_float4(u[0], u[1], u[2], asum);
}

// ---- Pass 7: Sobel, alpha blend, clip, mu ----
__global__ __launch_bounds__(256) void k_sobel_mu(const float* __restrict__ A) {
    const float SIGMA = 0.65f, MAB = 4.35f, DT = 0.2f;
    int i = blockIdx.x * 256 + threadIdx.x;
    int x = i >> 8, y = i & 255;
    float4 S[3][3];
#pragma unroll
    for (int du = 0; du < 3; du++)
#pragma unroll
        for (int dv = 0; dv < 3; dv++) {
            int xx = x + du - 1, yy = y + dv - 1;
            bool ok = (unsigned)xx < 256u && (unsigned)yy < 256u;
            S[du][dv] = ok ? g_UcAs[xx * 256 + yy] : make_float4(0.f, 0.f, 0.f, 0.f);
        }
    float gy[4], gx[4];
    {
        float4 b0 = S[2][0], b1 = S[2][1], b2 = S[2][2];
        float4 t0 = S[0][0], t1 = S[0][1], t2 = S[0][2];
        gy[0] = (b0.x + 2.f * b1.x + b2.x) - (t0.x + 2.f * t1.x + t2.x);
        gy[1] = (b0.y + 2.f * b1.y + b2.y) - (t0.y + 2.f * t1.y + t2.y);
        gy[2] = (b0.z + 2.f * b1.z + b2.z) - (t0.z + 2.f * t1.z + t2.z);
        gy[3] = (b0.w + 2.f * b1.w + b2.w) - (t0.w + 2.f * t1.w + t2.w);
        float4 r0 = S[0][2], r1 = S[1][2], r2 = S[2][2];
        float4 l0 = S[0][0], l1 = S[1][0], l2 = S[2][0];
        gx[0] = (r0.x + 2.f * r1.x + r2.x) - (l0.x + 2.f * l1.x + l2.x);
        gx[1] = (r0.y + 2.f * r1.y + r2.y) - (l0.y + 2.f * l1.y + l2.y);
        gx[2] = (r0.z + 2.f * r1.z + r2.z) - (l0.z + 2.f * l1.z + l2.z);
        gx[3] = (r0.w + 2.f * r1.w + r2.w) - (l0.w + 2.f * l1.w + l2.w);
    }
    float pr = (float)x + 0.5f, pc = (float)y + 0.5f;
#pragma unroll
    for (int c = 0; c < 3; c++) {
        float a = A[i * 3 + c];
        float al = fminf(0.25f * a * a, 1.0f);
        float Fy = gy[c] * (1.0f - al) - gy[3] * al;
        float Fx = gx[c] * (1.0f - al) - gx[3] * al;
        Fy = fminf(fmaxf(Fy, -MAB), MAB);
        Fx = fminf(fmaxf(Fx, -MAB), MAB);
        float mur = fminf(fmaxf(pr + DT * Fy, SIGMA), 256.0f - SIGMA);
        float muc = fminf(fmaxf(pc + DT * Fx, SIGMA), 256.0f - SIGMA);
        g_mu[i * 6 + c]     = mur;
        g_mu[i * 6 + 3 + c] = muc;
    }
}

// ---- Pass 8: reintegration gather (25-source window), softmax-mixed P ----
__global__ __launch_bounds__(256) void k_reint(const float* __restrict__ A,
                                               const float* __restrict__ P,
                                               float* __restrict__ outA,
                                               float* __restrict__ outP) {
    const float SIGMA = 0.65f;
    const float INV4S2 = 1.0f / (4.0f * 0.65f * 0.65f);
    __shared__ float s_mu[400 * 6];
    __shared__ float s_A[400 * 3];
    __shared__ float s_P[400 * 15];
    int x0 = blockIdx.y * 16;
    int y0 = blockIdx.x * 16;
    int tid = threadIdx.x;
    for (int cidx = tid; cidx < 400; cidx += 256) {
        int ti = cidx / 20, tj = cidx - ti * 20;
        int gx = x0 + ti - 2, gy = y0 + tj - 2;
        bool ok = (unsigned)gx < 256u && (unsigned)gy < 256u;
        int gi = gx * 256 + gy;
#pragma unroll
        for (int f = 0; f < 6; f++) s_mu[cidx * 6 + f] = ok ? g_mu[gi * 6 + f] : -1.0e4f;
#pragma unroll
        for (int c = 0; c < 3; c++) s_A[cidx * 3 + c] = ok ? A[gi * 3 + c] : 0.0f;
#pragma unroll
        for (int k = 0; k < 15; k++) s_P[cidx * 15 + k] = ok ? P[gi * 15 + k] : 0.0f;
    }
    __syncthreads();

    int li = tid >> 4, lj = tid & 15;
    int x = x0 + li, y = y0 + lj;
    float pr = (float)x + 0.5f, pc = (float)y + 0.5f;
    float accA[3] = {0.f, 0.f, 0.f};
    float num[15];
#pragma unroll
    for (int k = 0; k < 15; k++) num[k] = 0.0f;
    float den = 0.0f;

    for (int di = 0; di < 5; di++) {
#pragma unroll
        for (int dj = 0; dj < 5; dj++) {
            int cell = (li + di) * 20 + (lj + dj);
            const float* mu = &s_mu[cell * 6];
            float ssum = 0.0f;
#pragma unroll
            for (int c = 0; c < 3; c++) {
                float szr = 0.5f + SIGMA - fabsf(pr - mu[c]);
                float szc = 0.5f + SIGMA - fabsf(pc - mu[3 + c]);
                float ar = fminf(fmaxf(szr, 0.0f), 1.0f) *
                           fminf(fmaxf(szc, 0.0f), 1.0f) * INV4S2;
                float nA = s_A[cell * 3 + c] * ar;
                accA[c] += nA;
                ssum += nA;
            }
            float e = expf(ssum) - 1.0f;
            den += e;
#pragma unroll
            for (int k = 0; k < 15; k++) num[k] += s_P[cell * 15 + k] * e;
        }
    }
    int gi = x * 256 + y;
#pragma unroll
    for (int c = 0; c < 3; c++) outA[gi * 3 + c] = accA[c];
    float inv = 1.0f / (den + 1e-10f);
#pragma unroll
    for (int k = 0; k < 15; k++) outP[gi * 15 + k] = num[k] * inv;
}

extern "C" void kernel_launch(void* const* d_in, const int* in_sizes, int n_in,
                              void* d_out, int out_size) {
    const float* A   = (const float*)d_in[0];
    const float* P   = (const float*)d_in[1];
    const float* fKr = (const float*)d_in[2];
    const float* fKi = (const float*)d_in[3];
    const float* m   = (const float*)d_in[4];
    const float* s   = (const float*)d_in[5];
    float* outA = (float*)d_out;
    float* outP = (float*)d_out + 256 * 256 * 3;

    k_fwd_rows<<<128, 256>>>(A);
    k_fwd_cols<<<128, 256>>>();
    k_spec<<<256, 256>>>(fKr, fKi);
    k_inv_rows<<<512, 256>>>();
    k_inv_cols<<<512, 256>>>(m, s);
    k_ucas<<<256, 256>>>(A, P);
    k_sobel_mu<<<256, 256>>>(A);
    k_reint<<<dim3(16, 16), 256>>>(A, P, outA, outP);
}

// round 5
// speedup vs baseline: 1.2982x; 1.0433x over previous
#include <cuda_runtime.h>

// FlowLenia single step. SX=SY=256, C=3, K=15, DD=5, DT=0.2, SIGMA=0.65
// Output: newA (256*256*3) followed by newP (256*256*15), float32.
//
// R5: fuse spectral multiply into inverse-row FFT; fuse ucas+sobel with
//     halo tile; float4 P accumulation in reintegration. 6 kernels.

#define NPIX 65536
static __device__ float4 g_F4[NPIX];          // 2 planes of float2
static __device__ float4 g_tmp4[4 * NPIX];    // 8 planes of float2
#define G_F   ((float2*)g_F4)
#define G_TMP ((float2*)g_tmp4)
static __device__ float  g_G[15 * NPIX];      // growth(U), [k][x][y]
static __device__ float  g_mu[NPIX * 6];      // [row_c0..2, col_c0..2]

__device__ __forceinline__ float2 cmulf(float2 a, float2 b) {
    return make_float2(a.x * b.x - a.y * b.y, a.x * b.y + a.y * b.x);
}
__device__ __forceinline__ float2 cadd(float2 a, float2 b) {
    return make_float2(a.x + b.x, a.y + b.y);
}
__device__ __forceinline__ float2 csub(float2 a, float2 b) {
    return make_float2(a.x - b.x, a.y - b.y);
}
__device__ __forceinline__ int brev5(int l) {
    return ((l & 1) << 4) | ((l & 2) << 2) | (l & 4) | ((l & 8) >> 2) | ((l & 16) >> 4);
}

// 256-pt FFT across a 64-thread group (t = tid&63), v[r] = x[t + 64r].
// Output: thread t, reg q holds X[q + 4*(t>>5) + 8*brev5(t&31)].
// xch: 4*66 float2 scratch per group. Contains ONE block-wide __syncthreads.
template <bool INV>
__device__ __forceinline__ void group_fft256(float2 v[4], float2* xch, int t) {
    const float SGN = INV ? 1.0f : -1.0f;
    int l = t & 31;
    int w = t >> 5;
    float2 e0 = cadd(v[0], v[2]);
    float2 e1 = csub(v[0], v[2]);
    float2 o0 = cadd(v[1], v[3]);
    float2 o1 = csub(v[1], v[3]);
    float2 io1 = make_float2(-SGN * o1.y, SGN * o1.x);
    v[0] = cadd(e0, o0);
    v[2] = csub(e0, o0);
    v[1] = cadd(e1, io1);
    v[3] = csub(e1, io1);
    float sn, cs;
    sincospif(SGN * (float)t * (1.0f / 128.0f), &sn, &cs);
    float2 w1 = make_float2(cs, sn);
    float2 w2 = cmulf(w1, w1);
    float2 w3 = cmulf(w2, w1);
    v[1] = cmulf(v[1], w1);
    v[2] = cmulf(v[2], w2);
    v[3] = cmulf(v[3], w3);
#pragma unroll
    for (int q = 0; q < 4; q++) xch[q * 66 + t] = v[q];
    __syncthreads();
    {
        int pt = t ^ 32;
        sincospif(SGN * (float)l * (1.0f / 32.0f), &sn, &cs);
        float2 wt = make_float2(cs, sn);
#pragma unroll
        for (int q = 0; q < 4; q++) {
            float2 p = xch[q * 66 + pt];
            if (w == 0) v[q] = cadd(v[q], p);
            else        v[q] = cmulf(csub(p, v[q]), wt);
        }
    }
#pragma unroll
    for (int s5 = 0; s5 < 5; s5++) {
        int h = 16 >> s5;
        int e = (l & (h - 1)) << s5;
        sincospif(SGN * (float)e * (1.0f / 16.0f), &sn, &cs);
        float2 tw = make_float2(cs, sn);
        bool up = (l & h) != 0;
#pragma unroll
        for (int q = 0; q < 4; q++) {
            float2 p;
            p.x = __shfl_xor_sync(0xffffffffu, v[q].x, h);
            p.y = __shfl_xor_sync(0xffffffffu, v[q].y, h);
            if (up) v[q] = cmulf(csub(p, v[q]), tw);
            else    v[q] = cadd(v[q], p);
        }
    }
}

__device__ __forceinline__ int out_k0(int t) {
    return ((t >> 5) << 2) + 8 * brev5(t & 31);
}

// ---- Pass 1: forward row FFT (along y). plane0 = A0+i*A1, plane1 = A2 ----
__global__ __launch_bounds__(256) void k_fwd_rows(const float* __restrict__ A) {
    __shared__ float2 xch[4][4 * 66];
    int tid = threadIdx.x;
    int g = tid >> 6, t = tid & 63;
    int gid = blockIdx.x * 4 + g;   // 0..511
    int plane = gid >> 8;
    int x = gid & 255;
    float2 v[4];
#pragma unroll
    for (int r = 0; r < 4; r++) {
        int gi = (x * 256 + t + 64 * r) * 3;
        v[r] = (plane == 0) ? make_float2(A[gi], A[gi + 1])
                            : make_float2(A[gi + 2], 0.0f);
    }
    group_fft256<false>(v, xch[g], t);
    int k0 = out_k0(t);
    float4* out = (float4*)(G_F + plane * NPIX + x * 256 + k0);
    out[0] = make_float4(v[0].x, v[0].y, v[1].x, v[1].y);
    out[1] = make_float4(v[2].x, v[2].y, v[3].x, v[3].y);
}

// ---- Pass 2: forward column FFT (along x), 4 columns per 256-thr block ----
__global__ __launch_bounds__(256) void k_fwd_cols() {
    __shared__ float2 stage[4 * 292];
    __shared__ float2 xch[4][4 * 66];
    int b = blockIdx.x;             // 2*64
    int plane = b >> 6;
    int y0 = (b & 63) * 4;
    float2* base = G_F + plane * NPIX;
    int tid = threadIdx.x;
    for (int i = tid; i < 1024; i += 256)
        stage[(i & 3) * 292 + (i >> 2)] = base[(i >> 2) * 256 + y0 + (i & 3)];
    __syncthreads();
    int g = tid >> 6, t = tid & 63;
    float2 v[4];
#pragma unroll
    for (int r = 0; r < 4; r++) v[r] = stage[g * 292 + t + 64 * r];
    group_fft256<false>(v, xch[g], t);
    int k0 = out_k0(t);
#pragma unroll
    for (int q = 0; q < 4; q++) {
        int k = k0 + q;
        stage[g * 292 + k + (k >> 3)] = v[q];
    }
    __syncthreads();
    for (int i = tid; i < 1024; i += 256) {
        int x = i >> 2, jj = i & 3;
        base[x * 256 + y0 + jj] = stage[jj * 292 + x + (x >> 3)];
    }
}

// ---- Pass 3: spectral multiply (Hermitian unpack) + inverse row FFT ----
// Z_j = H_{2j} + i*H_{2j+1}, H_k = fK_k * fA_{k%3}. Planar output to g_tmp.
__global__ __launch_bounds__(256) void k_inv_rows(const float* __restrict__ fKr,
                                                  const float* __restrict__ fKi) {
    __shared__ float2 xch[4][4 * 66];
    int tid = threadIdx.x;
    int g = tid >> 6, t = tid & 63;
    int gid = blockIdx.x * 4 + g;   // 0..2047
    int j = gid >> 8, x = gid & 255;
    int k1 = 2 * j, k2 = 2 * j + 1;
    bool k2v = (j < 7);
    int c1 = k1 % 3, c2 = k2 % 3;
    int xr = (256 - x) & 255;
    float2 v[4];
#pragma unroll
    for (int r = 0; r < 4; r++) {
        int y = t + 64 * r;
        int gi = x * 256 + y;
        int yr = (256 - y) & 255;
        float2 fv = G_F[gi];
        float2 fr = G_F[xr * 256 + yr];
        float2 fa0 = make_float2(0.5f * (fv.x + fr.x), 0.5f * (fv.y - fr.y));
        float2 fa1 = make_float2(0.5f * (fv.y + fr.y), 0.5f * (fr.x - fv.x));
        float2 fa2 = G_F[NPIX + gi];
        float2 fc1 = (c1 == 0) ? fa0 : ((c1 == 1) ? fa1 : fa2);
        float2 H1 = cmulf(make_float2(fKr[gi * 15 + k1], fKi[gi * 15 + k1]), fc1);
        float2 H2 = make_float2(0.f, 0.f);
        if (k2v) {
            float2 fc2 = (c2 == 0) ? fa0 : ((c2 == 1) ? fa1 : fa2);
            H2 = cmulf(make_float2(fKr[gi * 15 + k2], fKi[gi * 15 + k2]), fc2);
        }
        v[r] = make_float2(H1.x - H2.y, H1.y + H2.x);
    }
    group_fft256<true>(v, xch[g], t);
    int k0 = out_k0(t);
    float4* out = (float4*)(G_TMP + j * NPIX + x * 256 + k0);
    out[0] = make_float4(v[0].x, v[0].y, v[1].x, v[1].y);
    out[1] = make_float4(v[2].x, v[2].y, v[3].x, v[3].y);
}

// ---- Pass 4: inverse column FFT + growth -> g_G[k1], g_G[k2] ----
__global__ __launch_bounds__(256) void k_inv_cols(const float* __restrict__ m,
                                                  const float* __restrict__ s) {
    __shared__ float2 stage[4 * 292];
    __shared__ float2 xch[4][4 * 66];
    int b = blockIdx.x;             // 8*64
    int j = b >> 6;
    int y0 = (b & 63) * 4;
    int k1 = 2 * j, k2 = 2 * j + 1;
    bool k2v = (j < 7);
    float2* base = G_TMP + j * NPIX;
    int tid = threadIdx.x;
    for (int i = tid; i < 1024; i += 256)
        stage[(i & 3) * 292 + (i >> 2)] = base[(i >> 2) * 256 + y0 + (i & 3)];
    __syncthreads();
    int g = tid >> 6, t = tid & 63;
    float2 v[4];
#pragma unroll
    for (int r = 0; r < 4; r++) v[r] = stage[g * 292 + t + 64 * r];
    group_fft256<true>(v, xch[g], t);
    float m1 = m[k1], s1 = s[k1];
    float i2s1 = 1.0f / (2.0f * s1 * s1);
    float m2 = k2v ? m[k2] : 0.f, s2 = k2v ? s[k2] : 1.f;
    float i2s2 = 1.0f / (2.0f * s2 * s2);
    int k0 = out_k0(t);
#pragma unroll
    for (int q = 0; q < 4; q++) {
        float u1 = v[q].x * (1.0f / 65536.0f);
        float t1 = u1 - m1;
        float g1 = 2.0f * expf(-t1 * t1 * i2s1) - 1.0f;
        float u2 = v[q].y * (1.0f / 65536.0f);
        float t2 = u2 - m2;
        float g2 = 2.0f * expf(-t2 * t2 * i2s2) - 1.0f;
        int k = k0 + q;
        stage[g * 292 + k + (k >> 3)] = make_float2(g1, g2);
    }
    __syncthreads();
    for (int i = tid; i < 1024; i += 256) {
        int x = i >> 2, jj = i & 3;
        float2 val = stage[jj * 292 + x + (x >> 3)];
        int gi = x * 256 + y0 + jj;
        g_G[k1 * NPIX + gi] = val.x;
        if (k2v) g_G[k2 * NPIX + gi] = val.y;
    }
}

// ---- Pass 5: fused UcAs (18x18 halo tile) + Sobel + mu ----
__global__ __launch_bounds__(256) void k_ucas_sobel(const float* __restrict__ A,
                                                    const float* __restrict__ P) {
    const float SIGMA = 0.65f, MAB = 4.35f, DT = 0.2f;
    __shared__ float4 sU[18 * 18];
    int x0 = blockIdx.y * 16;
    int y0 = blockIdx.x * 16;
    int tid = threadIdx.x;
    for (int i = tid; i < 324; i += 256) {
        int ti = i / 18, tj = i - ti * 18;
        int gx = x0 + ti - 1, gy = y0 + tj - 1;
        float4 val = make_float4(0.f, 0.f, 0.f, 0.f);
        if ((unsigned)gx < 256u && (unsigned)gy < 256u) {
            int gi = gx * 256 + gy;
            float u[3] = {0.f, 0.f, 0.f};
#pragma unroll
            for (int k = 0; k < 15; k++) u[k % 3] += g_G[k * NPIX + gi] * P[gi * 15 + k];
            val = make_float4(u[0], u[1], u[2],
                              A[gi * 3 + 0] + A[gi * 3 + 1] + A[gi * 3 + 2]);
        }
        sU[i] = val;
    }
    __syncthreads();
    int li = tid >> 4, lj = tid & 15;
    int x = x0 + li, y = y0 + lj;
    int i = x * 256 + y;
    float4 S[3][3];
#pragma unroll
    for (int du = 0; du < 3; du++)
#pragma unroll
        for (int dv = 0; dv < 3; dv++)
            S[du][dv] = sU[(li + du) * 18 + (lj + dv)];
    float gy[4], gx[4];
    {
        float4 b0 = S[2][0], b1 = S[2][1], b2 = S[2][2];
        float4 t0 = S[0][0], t1 = S[0][1], t2 = S[0][2];
        gy[0] = (b0.x + 2.f * b1.x + b2.x) - (t0.x + 2.f * t1.x + t2.x);
        gy[1] = (b0.y + 2.f * b1.y + b2.y) - (t0.y + 2.f * t1.y + t2.y);
        gy[2] = (b0.z + 2.f * b1.z + b2.z) - (t0.z + 2.f * t1.z + t2.z);
        gy[3] = (b0.w + 2.f * b1.w + b2.w) - (t0.w + 2.f * t1.w + t2.w);
        float4 r0 = S[0][2], r1 = S[1][2], r2 = S[2][2];
        float4 l0 = S[0][0], l1 = S[1][0], l2 = S[2][0];
        gx[0] = (r0.x + 2.f * r1.x + r2.x) - (l0.x + 2.f * l1.x + l2.x);
        gx[1] = (r0.y + 2.f * r1.y + r2.y) - (l0.y + 2.f * l1.y + l2.y);
        gx[2] = (r0.z + 2.f * r1.z + r2.z) - (l0.z + 2.f * l1.z + l2.z);
        gx[3] = (r0.w + 2.f * r1.w + r2.w) - (l0.w + 2.f * l1.w + l2.w);
    }
    float pr = (float)x + 0.5f, pc = (float)y + 0.5f;
#pragma unroll
    for (int c = 0; c < 3; c++) {
        float a = A[i * 3 + c];
        float al = fminf(0.25f * a * a, 1.0f);
        float Fy = gy[c] * (1.0f - al) - gy[3] * al;
        float Fx = gx[c] * (1.0f - al) - gx[3] * al;
        Fy = fminf(fmaxf(Fy, -MAB), MAB);
        Fx = fminf(fmaxf(Fx, -MAB), MAB);
        float mur = fminf(fmaxf(pr + DT * Fy, SIGMA), 256.0f - SIGMA);
        float muc = fminf(fmaxf(pc + DT * Fx, SIGMA), 256.0f - SIGMA);
        g_mu[i * 6 + c]     = mur;
        g_mu[i * 6 + 3 + c] = muc;
    }
}

// ---- Pass 6: reintegration gather (25-source window), softmax-mixed P ----
__global__ __launch_bounds__(256) void k_reint(const float* __restrict__ A,
                                               const float* __restrict__ P,
                                               float* __restrict__ outA,
                                               float* __restrict__ outP) {
    const float SIGMA = 0.65f;
    const float INV4S2 = 1.0f / (4.0f * 0.65f * 0.65f);
    __shared__ float s_mu[400 * 6];
    __shared__ float s_A[400 * 3];
    __shared__ __align__(16) float s_P[400 * 20];
    int x0 = blockIdx.y * 16;
    int y0 = blockIdx.x * 16;
    int tid = threadIdx.x;
    for (int cidx = tid; cidx < 400; cidx += 256) {
        int ti = cidx / 20, tj = cidx - ti * 20;
        int gx = x0 + ti - 2, gy = y0 + tj - 2;
        bool ok = (unsigned)gx < 256u && (unsigned)gy < 256u;
        int gi = gx * 256 + gy;
#pragma unroll
        for (int f = 0; f < 6; f++) s_mu[cidx * 6 + f] = ok ? g_mu[gi * 6 + f] : -1.0e4f;
#pragma unroll
        for (int c = 0; c < 3; c++) s_A[cidx * 3 + c] = ok ? A[gi * 3 + c] : 0.0f;
#pragma unroll
        for (int k = 0; k < 15; k++) s_P[cidx * 20 + k] = ok ? P[gi * 15 + k] : 0.0f;
        s_P[cidx * 20 + 15] = 0.0f;
    }
    __syncthreads();

    int li = tid >> 4, lj = tid & 15;
    int x = x0 + li, y = y0 + lj;
    float pr = (float)x + 0.5f, pc = (float)y + 0.5f;
    float accA[3] = {0.f, 0.f, 0.f};
    float4 n0 = make_float4(0.f, 0.f, 0.f, 0.f), n1 = n0, n2 = n0, n3 = n0;
    float den = 0.0f;

    for (int di = 0; di < 5; di++) {
#pragma unroll
        for (int dj = 0; dj < 5; dj++) {
            int cell = (li + di) * 20 + (lj + dj);
            const float* mu = &s_mu[cell * 6];
            float ssum = 0.0f;
#pragma unroll
            for (int c = 0; c < 3; c++) {
                float szr = 0.5f + SIGMA - fabsf(pr - mu[c]);
                float szc = 0.5f + SIGMA - fabsf(pc - mu[3 + c]);
                float ar = fminf(fmaxf(szr, 0.0f), 1.0f) *
                           fminf(fmaxf(szc, 0.0f), 1.0f) * INV4S2;
                float nA = s_A[cell * 3 + c] * ar;
                accA[c] += nA;
                ssum += nA;
            }
            float e = expf(ssum) - 1.0f;
            den += e;
            const float4* p4 = (const float4*)(s_P + cell * 20);
            float4 a0 = p4[0], a1 = p4[1], a2 = p4[2], a3 = p4[3];
            n0.x += a0.x * e; n0.y += a0.y * e; n0.z += a0.z * e; n0.w += a0.w * e;
            n1.x += a1.x * e; n1.y += a1.y * e; n1.z += a1.z * e; n1.w += a1.w * e;
            n2.x += a2.x * e; n2.y += a2.y * e; n2.z += a2.z * e; n2.w += a2.w * e;
            n3.x += a3.x * e; n3.y += a3.y * e; n3.z += a3.z * e;
        }
    }
    int gi = x * 256 + y;
#pragma unroll
    for (int c = 0; c < 3; c++) outA[gi * 3 + c] = accA[c];
    float inv = 1.0f / (den + 1e-10f);
    float num[15] = {n0.x, n0.y, n0.z, n0.w, n1.x, n1.y, n1.z, n1.w,
                     n2.x, n2.y, n2.z, n2.w, n3.x, n3.y, n3.z};
#pragma unroll
    for (int k = 0; k < 15; k++) outP[gi * 15 + k] = num[k] * inv;
}

extern "C" void kernel_launch(void* const* d_in, const int* in_sizes, int n_in,
                              void* d_out, int out_size) {
    const float* A   = (const float*)d_in[0];
    const float* P   = (const float*)d_in[1];
    const float* fKr = (const float*)d_in[2];
    const float* fKi = (const float*)d_in[3];
    const float* m   = (const float*)d_in[4];
    const float* s   = (const float*)d_in[5];
    float* outA = (float*)d_out;
    float* outP = (float*)d_out + 256 * 256 * 3;

    k_fwd_rows<<<128, 256>>>(A);
    k_fwd_cols<<<128, 256>>>();
    k_inv_rows<<<512, 256>>>(fKr, fKi);
    k_inv_cols<<<512, 256>>>(m, s);
    k_ucas_sobel<<<dim3(16, 16), 256>>>(A, P);
    k_reint<<<dim3(16, 16), 256>>>(A, P, outA, outP);
}